// round 3
// baseline (speedup 1.0000x reference)
#include <cuda_runtime.h>
#include <cuda_bf16.h>
#include <cstdint>

// HighOrderActivation: simplex interpolation over K=4 corners of a 2^4 table.
// X: [B=1024, D=512, 4] f32, params: [D=512, 16, 64] f32, out: [B, D, 64] f32.
//
// Per (b,d): argsort 4 X values ascending;
//   c0 = xs0, c1 = xs1-xs0, c2 = xs2-xs1, c3 = xs3-xs2
//   ind0 = 15 (constant!), ind1 = 15-(1<<i0), ind2 = ind1-(1<<i1), ind3 = 1<<i3
//   out[b,d,:] = sum_j c_j * params[d, ind_j, :]
//
// Blocking: grid = (B/BCHUNK, D). Each block owns ONE d; params[d] (4 KB) is
// staged in smem once (L2 param traffic 512 MB -> 8 MB). Row 15 (always
// needed) is additionally cached in registers, cutting LDS traffic 25%.
// 8 threads per (b,d) pair; each thread produces TWO float4s of the 64-float
// output row, amortizing the sort/index work and the X load.

#define B_DIM  1024
#define D_DIM  512
#define TBL_ROWS 16
#define BCHUNK 256              // b's per block
#define THREADS_PER_BLOCK 256   // 32 pairs per loop iteration (8 thr/pair)
#define PAIRS_PER_ITER (THREADS_PER_BLOCK / 8)      // 32
#define ITERS (BCHUNK / PAIRS_PER_ITER)             // 8

__global__ __launch_bounds__(THREADS_PER_BLOCK)
void hoa_kernel(const float* __restrict__ X,
                const float* __restrict__ params,
                float* __restrict__ out)
{
    __shared__ float4 tab[TBL_ROWS * 16];   // 16 rows x 16 float4 = 4 KB

    const int tid = threadIdx.x;
    const int d   = blockIdx.y;
    const int b0  = blockIdx.x * BCHUNK;

    // Stage params[d] into smem: 256 float4 = one per thread.
    tab[tid] = reinterpret_cast<const float4*>(params)[(size_t)d * (TBL_ROWS * 16) + tid];
    __syncthreads();

    const int o         = tid & 7;    // thread owns float4 slots o and o+8
    const int pair_base = tid >> 3;   // 0..31 within iteration

    // Row 15 is used by EVERY output: cache this thread's two float4s in regs.
    const float4 r15a = tab[15 * 16 + o];
    const float4 r15b = tab[15 * 16 + o + 8];

    #pragma unroll 2
    for (int it = 0; it < ITERS; ++it) {
        const int b = b0 + it * PAIRS_PER_ITER + pair_base;
        const size_t p = (size_t)b * D_DIM + d;

        // X[b,d,0..3]: one 16B load, broadcast across the 8 threads of the pair.
        float4 xv = reinterpret_cast<const float4*>(X)[p];

        float v0 = xv.x, v1 = xv.y, v2 = xv.z, v3 = xv.w;
        int   i0 = 0,    i1 = 1,    i2 = 2,    i3 = 3;

        // 5-comparator sorting network (ascending), stable on ties.
#define CSWAP(a, b_, ia, ib)                             \
        do {                                             \
            if ((a) > (b_)) {                            \
                float tv = (a); (a) = (b_); (b_) = tv;   \
                int   ti = (ia); (ia) = (ib); (ib) = ti; \
            }                                            \
        } while (0)
        CSWAP(v0, v1, i0, i1);
        CSWAP(v2, v3, i2, i3);
        CSWAP(v0, v2, i0, i2);
        CSWAP(v1, v3, i1, i3);
        CSWAP(v1, v2, i1, i2);
#undef CSWAP

        // Corner indices: reverse cumsum of bit masks (ind0 == 15 always).
        const int ind1 = 15 - (1 << i0);
        const int ind2 = ind1 - (1 << i1);
        const int ind3 = (1 << i3);

        // Simplex coefficients.
        const float c0 = v0;
        const float c1 = v1 - v0;
        const float c2 = v2 - v1;
        const float c3 = v3 - v2;

        // Gather 3 rows x 2 slots from smem (LDS.128, conflict-free).
        const float4 g1a = tab[ind1 * 16 + o];
        const float4 g1b = tab[ind1 * 16 + o + 8];
        const float4 g2a = tab[ind2 * 16 + o];
        const float4 g2b = tab[ind2 * 16 + o + 8];
        const float4 g3a = tab[ind3 * 16 + o];
        const float4 g3b = tab[ind3 * 16 + o + 8];

        float4 ra, rb;
        ra.x = c0 * r15a.x + c1 * g1a.x + c2 * g2a.x + c3 * g3a.x;
        ra.y = c0 * r15a.y + c1 * g1a.y + c2 * g2a.y + c3 * g3a.y;
        ra.z = c0 * r15a.z + c1 * g1a.z + c2 * g2a.z + c3 * g3a.z;
        ra.w = c0 * r15a.w + c1 * g1a.w + c2 * g2a.w + c3 * g3a.w;

        rb.x = c0 * r15b.x + c1 * g1b.x + c2 * g2b.x + c3 * g3b.x;
        rb.y = c0 * r15b.y + c1 * g1b.y + c2 * g2b.y + c3 * g3b.y;
        rb.z = c0 * r15b.z + c1 * g1b.z + c2 * g2b.z + c3 * g3b.z;
        rb.w = c0 * r15b.w + c1 * g1b.w + c2 * g2b.w + c3 * g3b.w;

        // Two STG.E.128 per thread; 8 threads of a pair cover the 256 B row
        // as two fully-coalesced 128 B segments each.
        float4* orow = reinterpret_cast<float4*>(out) + p * 16;
        orow[o]     = ra;
        orow[o + 8] = rb;
    }
}

extern "C" void kernel_launch(void* const* d_in, const int* in_sizes, int n_in,
                              void* d_out, int out_size)
{
    const float* X      = (const float*)d_in[0];   // [B, D, 4] f32
    const float* params = (const float*)d_in[1];   // [D, 16, 64] f32
    float*       out    = (float*)d_out;           // [B, D, 64] f32

    dim3 grid(B_DIM / BCHUNK, D_DIM);              // (4, 512) = 2048 blocks
    hoa_kernel<<<grid, THREADS_PER_BLOCK>>>(X, params, out);
}

// round 4
// speedup vs baseline: 1.0560x; 1.0560x over previous
#include <cuda_runtime.h>
#include <cuda_bf16.h>
#include <cstdint>

// HighOrderActivation: simplex interpolation over K=4 corners of a 2^4 table.
// X: [B=1024, D=512, 4] f32, params: [D=512, 16, 64] f32, out: [B, D, 64] f32.
//
// Per (b,d): argsort 4 X values ascending;
//   c0 = xs0, c1 = xs1-xs0, c2 = xs2-xs1, c3 = xs3-xs2
//   ind0 = 15 (constant), ind1 = 15-(1<<i0), ind2 = ind1-(1<<i1), ind3 = 1<<i3
//   out[b,d,:] = sum_j c_j * params[d, ind_j, :]
//
// Blocking: grid = (B/BCHUNK, D). Each block owns ONE d.
//  - params[d] (4 KB) staged in smem once  (L2 param traffic 512 MB -> 16 MB)
//  - X for the block's BCHUNK pairs (2 KB) staged in smem once, so the steady
//    state loop has NO global loads (kills the per-iter DRAM-latency stall)
//  - row 15 (needed by every output) cached in registers
// 8 threads per (b,d) pair; each thread produces TWO float4s of the output row.

#define B_DIM  1024
#define D_DIM  512
#define TBL_ROWS 16
#define BCHUNK 128              // b's per block
#define THREADS_PER_BLOCK 256
#define PAIRS_PER_ITER (THREADS_PER_BLOCK / 8)   // 32
#define ITERS (BCHUNK / PAIRS_PER_ITER)          // 4

__global__ __launch_bounds__(THREADS_PER_BLOCK, 6)
void hoa_kernel(const float* __restrict__ X,
                const float* __restrict__ params,
                float* __restrict__ out)
{
    __shared__ float4 tab[TBL_ROWS * 16];  // 16 rows x 16 float4 = 4 KB
    __shared__ float4 xs[BCHUNK];          // X for this block's pairs = 2 KB

    const int tid = threadIdx.x;
    const int d   = blockIdx.y;
    const int b0  = blockIdx.x * BCHUNK;

    // Stage params[d]: 256 float4 = one per thread.
    tab[tid] = reinterpret_cast<const float4*>(params)[(size_t)d * (TBL_ROWS * 16) + tid];
    // Stage X for the block's BCHUNK pairs (stride D_DIM float4 in gmem).
    if (tid < BCHUNK) {
        xs[tid] = reinterpret_cast<const float4*>(X)[(size_t)(b0 + tid) * D_DIM + d];
    }
    __syncthreads();

    const int o         = tid & 7;    // thread owns float4 slots o and o+8
    const int pair_base = tid >> 3;   // 0..31 within iteration

    // Row 15 cached in registers (used by every output).
    const float4 r15a = tab[15 * 16 + o];
    const float4 r15b = tab[15 * 16 + o + 8];

    #pragma unroll
    for (int it = 0; it < ITERS; ++it) {
        const int pr = it * PAIRS_PER_ITER + pair_base;   // 0..BCHUNK-1
        const size_t p = (size_t)(b0 + pr) * D_DIM + d;

        // Broadcast LDS: 8 threads of a pair read the same 16 B.
        float4 xv = xs[pr];

        float v0 = xv.x, v1 = xv.y, v2 = xv.z, v3 = xv.w;
        int   i0 = 0,    i1 = 1,    i2 = 2,    i3 = 3;

        // 5-comparator sorting network (ascending), stable on ties.
#define CSWAP(a, b_, ia, ib)                             \
        do {                                             \
            if ((a) > (b_)) {                            \
                float tv = (a); (a) = (b_); (b_) = tv;   \
                int   ti = (ia); (ia) = (ib); (ib) = ti; \
            }                                            \
        } while (0)
        CSWAP(v0, v1, i0, i1);
        CSWAP(v2, v3, i2, i3);
        CSWAP(v0, v2, i0, i2);
        CSWAP(v1, v3, i1, i3);
        CSWAP(v1, v2, i1, i2);
#undef CSWAP

        // Corner indices (ind0 == 15 always).
        const int ind1 = 15 - (1 << i0);
        const int ind2 = ind1 - (1 << i1);
        const int ind3 = (1 << i3);

        // Simplex coefficients.
        const float c0 = v0;
        const float c1 = v1 - v0;
        const float c2 = v2 - v1;
        const float c3 = v3 - v2;

        // Gather 3 rows x 2 slots from smem (LDS.128, conflict-free).
        const float4 g1a = tab[ind1 * 16 + o];
        const float4 g1b = tab[ind1 * 16 + o + 8];
        const float4 g2a = tab[ind2 * 16 + o];
        const float4 g2b = tab[ind2 * 16 + o + 8];
        const float4 g3a = tab[ind3 * 16 + o];
        const float4 g3b = tab[ind3 * 16 + o + 8];

        float4 ra, rb;
        ra.x = c0 * r15a.x + c1 * g1a.x + c2 * g2a.x + c3 * g3a.x;
        ra.y = c0 * r15a.y + c1 * g1a.y + c2 * g2a.y + c3 * g3a.y;
        ra.z = c0 * r15a.z + c1 * g1a.z + c2 * g2a.z + c3 * g3a.z;
        ra.w = c0 * r15a.w + c1 * g1a.w + c2 * g2a.w + c3 * g3a.w;

        rb.x = c0 * r15b.x + c1 * g1b.x + c2 * g2b.x + c3 * g3b.x;
        rb.y = c0 * r15b.y + c1 * g1b.y + c2 * g2b.y + c3 * g3b.y;
        rb.z = c0 * r15b.z + c1 * g1b.z + c2 * g2b.z + c3 * g3b.z;
        rb.w = c0 * r15b.w + c1 * g1b.w + c2 * g2b.w + c3 * g3b.w;

        // Two STG.E.128 per thread; pair covers its 256 B row as two
        // fully-coalesced 128 B segments.
        float4* orow = reinterpret_cast<float4*>(out) + p * 16;
        orow[o]     = ra;
        orow[o + 8] = rb;
    }
}

extern "C" void kernel_launch(void* const* d_in, const int* in_sizes, int n_in,
                              void* d_out, int out_size)
{
    const float* X      = (const float*)d_in[0];   // [B, D, 4] f32
    const float* params = (const float*)d_in[1];   // [D, 16, 64] f32
    float*       out    = (float*)d_out;           // [B, D, 64] f32

    dim3 grid(B_DIM / BCHUNK, D_DIM);              // (8, 512) = 4096 blocks
    hoa_kernel<<<grid, THREADS_PER_BLOCK>>>(X, params, out);
}